// round 13
// baseline (speedup 1.0000x reference)
#include <cuda_runtime.h>
#include <cstdint>

#define Bdim 2
#define Hdim 16
#define Sdim 2048
#define Ddim 128
#define QT 128            // q-tile rows per CTA
#define PH_KV 64          // kv rows per phase (32 per group)
#define NPH (Sdim / PH_KV)   // 32 phases
#define NTHREADS 256
#define WST 68            // fp16 tile word stride (ldmatrix conflict-free)

// smem word offsets (all fp16 tiles)
#define QS_OFF  0
#define K16_OFF (QT * WST)                    // 8704
#define V16_OFF (K16_OFF + 4 * 32 * WST)      // K16: 2grp x 2buf x 32 rows
#define SMEM_WORDS (V16_OFF + 4 * 32 * WST)
#define SMEM_BYTES (SMEM_WORDS * 4)           // 104448 B -> 1 CTA/SM

// ---------------------------------------------------------------------------
static __device__ __forceinline__ uint32_t h2(float lo, float hi) {
    uint32_t r;
    asm("cvt.rn.f16x2.f32 %0, %1, %2;" : "=r"(r) : "f"(hi), "f"(lo));
    return r;
}
// relu^2 in f16x2
static __device__ __forceinline__ uint32_t hsq(uint32_t w) {
    uint32_t r;
    asm("max.f16x2 %0, %1, %2;" : "=r"(r) : "r"(w), "r"(0u));
    asm("mul.f16x2 %0, %1, %1;" : "=r"(r) : "r"(r));
    return r;
}

static __device__ __forceinline__ void mma16(float* d,
        uint32_t a0, uint32_t a1, uint32_t a2, uint32_t a3,
        uint32_t b0, uint32_t b1) {
    asm volatile(
        "mma.sync.aligned.m16n8k16.row.col.f32.f16.f16.f32 "
        "{%0,%1,%2,%3}, {%4,%5,%6,%7}, {%8,%9}, {%0,%1,%2,%3};"
        : "+f"(d[0]), "+f"(d[1]), "+f"(d[2]), "+f"(d[3])
        : "r"(a0), "r"(a1), "r"(a2), "r"(a3), "r"(b0), "r"(b1));
}

static __device__ __forceinline__ void ldm4(uint32_t addr, uint32_t* r) {
    asm volatile("ldmatrix.sync.aligned.m8n8.x4.shared.b16 {%0,%1,%2,%3}, [%4];"
        : "=r"(r[0]), "=r"(r[1]), "=r"(r[2]), "=r"(r[3]) : "r"(addr));
}
static __device__ __forceinline__ void ldm4t(uint32_t addr, uint32_t* r) {
    asm volatile("ldmatrix.sync.aligned.m8n8.x4.trans.shared.b16 {%0,%1,%2,%3}, [%4];"
        : "=r"(r[0]), "=r"(r[1]), "=r"(r[2]), "=r"(r[3]) : "r"(addr));
}

static __device__ __forceinline__ void bar_sync(int id, int cnt) {
    asm volatile("bar.sync %0, %1;" :: "r"(id), "r"(cnt) : "memory");
}

// staged float4 -> fp16x4 STS at float4-index c (0..1023) of a 32x128 tile
static __device__ __forceinline__ void sts_h4(uint32_t* tile, int c, float4 f) {
    int r = c >> 5, j = c & 31;
    *reinterpret_cast<uint2*>(tile + r * WST + 2 * j) =
        make_uint2(h2(f.x, f.y), h2(f.z, f.w));
}
static __device__ __forceinline__ float4 ldg4(const float* base, int c) {
    int r = c >> 5, j = c & 31;
    return *reinterpret_cast<const float4*>(base + (size_t)r * Ddim + 4 * j);
}

// ---------------------------------------------------------------------------
// One CTA (256 thr, 8 warps) = one (b,h) x one 128-row q-tile. 1 CTA/SM.
// wm = wid&3 (m32 block), wn = wid>>2 (kv group, 32 rows/phase).
// K/V for tile t+1 stream as LDG->cvt->STS register waves (2 float4 = 8 regs
// peak) interleaved between GEMM sections. GEMM1 S(m32 x kv32) via ldmatrix;
// P = relu^2 f16x2 (C->A direct); GEMM2 O(m32 x d128) via ldmatrix.trans V
// (each V frag feeds 2 mma). One 128-wide named bar per phase per group.
// O reduced across the two groups at the end.
// ---------------------------------------------------------------------------
__global__ void __launch_bounds__(NTHREADS, 1)
attn_relu2_kernel(const float* __restrict__ q, const float* __restrict__ k,
                  const float* __restrict__ v, const float* __restrict__ scale_p,
                  float* __restrict__ out) {
    extern __shared__ uint32_t smw[];
    uint32_t* QW = smw + QS_OFF;

    const int tid  = threadIdx.x;
    const int lane = tid & 31;
    const int g    = lane >> 2;
    const int t4   = lane & 3;
    const int wid  = tid >> 5;
    const int wm   = wid & 3;      // m32 block
    const int wn   = wid >> 2;     // kv group
    const int tid_h = tid & 127;

    const int bh = blockIdx.x >> 4;
    const int q0 = (blockIdx.x & 15) << 7;

    const float* kbase = k + (size_t)bh * Sdim * Ddim;
    const float* vbase = v + (size_t)bh * Sdim * Ddim;

    // ldmatrix lane geometry
    const int rl8 = (((lane >> 3) & 1) << 3) + (lane & 7);
    const int c4  = ((lane >> 4) & 1) << 2;

    const uint32_t sb = (uint32_t)__cvta_generic_to_shared(smw);
    const uint32_t qa0 = sb + 4 * (QS_OFF + (wm * 32 + rl8) * WST + c4);
    const uint32_t qa1 = qa0 + 4 * 16 * WST;

    // ---- Q fill (scale folded, fp16, natural row-major) ----
    {
        const float scl = *scale_p;
        const float* qg = q + ((size_t)bh * Sdim + q0) * Ddim;
        #pragma unroll
        for (int i = 0; i < 16; i++) {
            int c = tid + NTHREADS * i;       // 0..4095
            int r = c >> 5, j = c & 31;
            float4 f = *reinterpret_cast<const float4*>(qg + r * Ddim + 4 * j);
            *reinterpret_cast<uint2*>(QW + r * WST + 2 * j) =
                make_uint2(h2(f.x * scl, f.y * scl), h2(f.z * scl, f.w * scl));
        }
    }

    // ---- prologue: tile 0 LDG -> cvt -> STS into buf 0 ----
    {
        const float* kg = kbase + (size_t)(wn * 32) * Ddim;
        const float* vg = vbase + (size_t)(wn * 32) * Ddim;
        uint32_t* kd = smw + K16_OFF + (wn * 2 + 0) * 32 * WST;
        uint32_t* vd = smw + V16_OFF + (wn * 2 + 0) * 32 * WST;
        #pragma unroll
        for (int i = 0; i < 8; i++) {
            int c = tid_h + 128 * i;          // 0..1023
            sts_h4(kd, c, ldg4(kg, c));
            sts_h4(vd, c, ldg4(vg, c));
        }
    }
    __syncthreads();

    float O[2][16][4];
    #pragma unroll
    for (int mb = 0; mb < 2; mb++)
        #pragma unroll
        for (int nd = 0; nd < 16; nd++)
            #pragma unroll
            for (int i = 0; i < 4; i++) O[mb][nd][i] = 0.0f;

    // ---- main loop: 32 phases ----
    #pragma unroll 1
    for (int t = 0; t < NPH; t++) {
        const int buf = t & 1;
        const bool more = (t + 1 < NPH);

        bar_sync(1 + wn, 128);   // fp16[buf] ready; prev reads of buf^1 done

        const float* kgn = kbase + (size_t)((t + 1) * PH_KV + wn * 32) * Ddim;
        const float* vgn = vbase + (size_t)((t + 1) * PH_KV + wn * 32) * Ddim;
        uint32_t* kd = smw + K16_OFF + (wn * 2 + (buf ^ 1)) * 32 * WST;
        uint32_t* vd = smw + V16_OFF + (wn * 2 + (buf ^ 1)) * 32 * WST;

        const uint32_t kb_b = sb + 4 * (K16_OFF + (wn * 2 + buf) * 32 * WST
                                        + rl8 * WST + c4);
        const uint32_t vb_b = sb + 4 * (V16_OFF + (wn * 2 + buf) * 32 * WST
                                        + rl8 * WST + c4);

        float4 sa, sb2;
        if (more) { sa = ldg4(kgn, tid_h); sb2 = ldg4(kgn, tid_h + 128); }

        // ---- GEMM1: S(m32 x kv32), 8 k16-steps, K waves interleaved ----
        float S[2][4][4];
        #pragma unroll
        for (int mb = 0; mb < 2; mb++)
            #pragma unroll
            for (int nb = 0; nb < 4; nb++)
                #pragma unroll
                for (int i = 0; i < 4; i++) S[mb][nb][i] = 0.0f;

        #pragma unroll
        for (int sec = 0; sec < 4; sec++) {
            #pragma unroll
            for (int kk = 0; kk < 2; kk++) {
                const int kb = sec * 2 + kk;
                uint32_t A0[4], A1[4], B0[4], B1[4];
                ldm4(qa0 + 32 * kb, A0);
                ldm4(qa1 + 32 * kb, A1);
                ldm4(kb_b + 32 * kb, B0);
                ldm4(kb_b + 4 * 16 * WST + 32 * kb, B1);
                mma16(S[0][0], A0[0], A0[1], A0[2], A0[3], B0[0], B0[2]);
                mma16(S[0][1], A0[0], A0[1], A0[2], A0[3], B0[1], B0[3]);
                mma16(S[0][2], A0[0], A0[1], A0[2], A0[3], B1[0], B1[2]);
                mma16(S[0][3], A0[0], A0[1], A0[2], A0[3], B1[1], B1[3]);
                mma16(S[1][0], A1[0], A1[1], A1[2], A1[3], B0[0], B0[2]);
                mma16(S[1][1], A1[0], A1[1], A1[2], A1[3], B0[1], B0[3]);
                mma16(S[1][2], A1[0], A1[1], A1[2], A1[3], B1[0], B1[2]);
                mma16(S[1][3], A1[0], A1[1], A1[2], A1[3], B1[1], B1[3]);
            }
            if (more) {
                // store completed K wave; start next wave (K waves 0..3, then V wave 0)
                sts_h4(kd, tid_h + 256 * sec, sa);
                sts_h4(kd, tid_h + 256 * sec + 128, sb2);
                if (sec < 3) {
                    sa  = ldg4(kgn, tid_h + 256 * (sec + 1));
                    sb2 = ldg4(kgn, tid_h + 256 * (sec + 1) + 128);
                } else {
                    sa  = ldg4(vgn, tid_h);
                    sb2 = ldg4(vgn, tid_h + 128);
                }
            }
        }

        // ---- P = relu(S)^2; GEMM2: O += P @ V, V waves interleaved ----
        #pragma unroll
        for (int s2 = 0; s2 < 2; s2++) {
            uint32_t pA[2][4];
            #pragma unroll
            for (int mb = 0; mb < 2; mb++) {
                pA[mb][0] = hsq(h2(S[mb][2 * s2][0],     S[mb][2 * s2][1]));
                pA[mb][1] = hsq(h2(S[mb][2 * s2][2],     S[mb][2 * s2][3]));
                pA[mb][2] = hsq(h2(S[mb][2 * s2 + 1][0], S[mb][2 * s2 + 1][1]));
                pA[mb][3] = hsq(h2(S[mb][2 * s2 + 1][2], S[mb][2 * s2 + 1][3]));
            }
            const uint32_t va_b = vb_b + 4 * 16 * WST * s2;
            #pragma unroll
            for (int half = 0; half < 2; half++) {
                #pragma unroll
                for (int j = 4 * half; j < 4 * half + 4; j++) {
                    uint32_t Vr[4];
                    ldm4t(va_b + 32 * j, Vr);
                    mma16(O[0][2 * j],     pA[0][0], pA[0][1], pA[0][2], pA[0][3], Vr[0], Vr[1]);
                    mma16(O[0][2 * j + 1], pA[0][0], pA[0][1], pA[0][2], pA[0][3], Vr[2], Vr[3]);
                    mma16(O[1][2 * j],     pA[1][0], pA[1][1], pA[1][2], pA[1][3], Vr[0], Vr[1]);
                    mma16(O[1][2 * j + 1], pA[1][0], pA[1][1], pA[1][2], pA[1][3], Vr[2], Vr[3]);
                }
                if (more) {
                    const int w = s2 * 2 + half;        // V wave 0..3
                    sts_h4(vd, tid_h + 256 * w, sa);
                    sts_h4(vd, tid_h + 256 * w + 128, sb2);
                    if (w < 3) {
                        sa  = ldg4(vgn, tid_h + 256 * (w + 1));
                        sb2 = ldg4(vgn, tid_h + 256 * (w + 1) + 128);
                    }
                }
            }
        }
    }

    // ---- reduce O across the two kv groups, write out ----
    __syncthreads();
    float* red = reinterpret_cast<float*>(smw);   // 128 x 132 floats
    if (wn == 1) {
        #pragma unroll
        for (int mb = 0; mb < 2; mb++) {
            int r0 = wm * 32 + mb * 16 + g;
            #pragma unroll
            for (int nd = 0; nd < 16; nd++) {
                *reinterpret_cast<float2*>(red + r0 * 132 + nd * 8 + 2 * t4) =
                    make_float2(O[mb][nd][0], O[mb][nd][1]);
                *reinterpret_cast<float2*>(red + (r0 + 8) * 132 + nd * 8 + 2 * t4) =
                    make_float2(O[mb][nd][2], O[mb][nd][3]);
            }
        }
    }
    __syncthreads();
    if (wn == 0) {
        float* ob = out + ((size_t)bh * Sdim + q0) * Ddim;
        #pragma unroll
        for (int mb = 0; mb < 2; mb++) {
            int r0 = wm * 32 + mb * 16 + g;
            #pragma unroll
            for (int nd = 0; nd < 16; nd++) {
                float2 ra = *reinterpret_cast<const float2*>(red + r0 * 132 + nd * 8 + 2 * t4);
                float2 rb = *reinterpret_cast<const float2*>(red + (r0 + 8) * 132 + nd * 8 + 2 * t4);
                *reinterpret_cast<float2*>(ob + r0 * Ddim + nd * 8 + 2 * t4) =
                    make_float2(O[mb][nd][0] + ra.x, O[mb][nd][1] + ra.y);
                *reinterpret_cast<float2*>(ob + (r0 + 8) * Ddim + nd * 8 + 2 * t4) =
                    make_float2(O[mb][nd][2] + rb.x, O[mb][nd][3] + rb.y);
            }
        }
    }
}

extern "C" void kernel_launch(void* const* d_in, const int* in_sizes, int n_in,
                              void* d_out, int out_size) {
    (void)in_sizes; (void)n_in; (void)out_size;
    const float* q = (const float*)d_in[0];
    const float* k = (const float*)d_in[1];
    const float* v = (const float*)d_in[2];
    const float* scale = (const float*)d_in[3];
    float* out = (float*)d_out;

    cudaFuncSetAttribute(attn_relu2_kernel,
                         cudaFuncAttributeMaxDynamicSharedMemorySize, SMEM_BYTES);

    dim3 grid(Bdim * Hdim * (Sdim / QT));   // 512 CTAs, bh-major
    attn_relu2_kernel<<<grid, NTHREADS, SMEM_BYTES>>>(q, k, v, scale, out);
}

// round 14
// speedup vs baseline: 1.9506x; 1.9506x over previous
#include <cuda_runtime.h>
#include <cstdint>

#define Bdim 2
#define Hdim 16
#define Sdim 2048
#define Ddim 128
#define QT 128            // q-tile rows per CTA
#define PH_KV 64          // kv rows per phase (32 per group)
#define NPH (Sdim / PH_KV)   // 32 phases
#define NTHREADS 256
#define WST 68            // fp16 tile word stride (ldmatrix conflict-free)

#define NTOT (Bdim * Hdim * Sdim * Ddim)      // 8388608 elements per tensor
#define NU2  (NTOT / 4)                       // uint2 (4 halfs) entries

// smem word offsets (all fp16 tiles)
#define QS_OFF  0
#define K16_OFF (QT * WST)                    // 8704
#define V16_OFF (K16_OFF + 4 * 32 * WST)      // K16: 2grp x 2buf x 32 rows
#define SMEM_WORDS (V16_OFF + 4 * 32 * WST)
#define SMEM_BYTES (SMEM_WORDS * 4)           // 104448 B -> 1 CTA/SM

// fp16 copies of Q*scale, K, V (written once by convert_kernel per launch)
__device__ uint2 QH[NU2];
__device__ uint2 KH[NU2];
__device__ uint2 VH[NU2];

// ---------------------------------------------------------------------------
static __device__ __forceinline__ uint32_t h2(float lo, float hi) {
    uint32_t r;
    asm("cvt.rn.f16x2.f32 %0, %1, %2;" : "=r"(r) : "f"(hi), "f"(lo));
    return r;
}
// relu^2 in f16x2
static __device__ __forceinline__ uint32_t hsq(uint32_t w) {
    uint32_t r;
    asm("max.f16x2 %0, %1, %2;" : "=r"(r) : "r"(w), "r"(0u));
    asm("mul.f16x2 %0, %1, %1;" : "=r"(r) : "r"(r));
    return r;
}

static __device__ __forceinline__ void mma16(float* d,
        uint32_t a0, uint32_t a1, uint32_t a2, uint32_t a3,
        uint32_t b0, uint32_t b1) {
    asm volatile(
        "mma.sync.aligned.m16n8k16.row.col.f32.f16.f16.f32 "
        "{%0,%1,%2,%3}, {%4,%5,%6,%7}, {%8,%9}, {%0,%1,%2,%3};"
        : "+f"(d[0]), "+f"(d[1]), "+f"(d[2]), "+f"(d[3])
        : "r"(a0), "r"(a1), "r"(a2), "r"(a3), "r"(b0), "r"(b1));
}

static __device__ __forceinline__ void ldm4(uint32_t addr, uint32_t* r) {
    asm volatile("ldmatrix.sync.aligned.m8n8.x4.shared.b16 {%0,%1,%2,%3}, [%4];"
        : "=r"(r[0]), "=r"(r[1]), "=r"(r[2]), "=r"(r[3]) : "r"(addr));
}
static __device__ __forceinline__ void ldm4t(uint32_t addr, uint32_t* r) {
    asm volatile("ldmatrix.sync.aligned.m8n8.x4.trans.shared.b16 {%0,%1,%2,%3}, [%4];"
        : "=r"(r[0]), "=r"(r[1]), "=r"(r[2]), "=r"(r[3]) : "r"(addr));
}

static __device__ __forceinline__ void cp16s(uint32_t* smem_dst, const void* gsrc) {
    unsigned sa = (unsigned)__cvta_generic_to_shared(smem_dst);
    asm volatile("cp.async.cg.shared.global [%0], [%1], 16;" :: "r"(sa), "l"(gsrc));
}
#define CP_COMMIT() asm volatile("cp.async.commit_group;" ::: "memory")
#define CP_WAIT0()  asm volatile("cp.async.wait_group 0;" ::: "memory")

static __device__ __forceinline__ void bar_sync(int id, int cnt) {
    asm volatile("bar.sync %0, %1;" :: "r"(id), "r"(cnt) : "memory");
}

// ---------------------------------------------------------------------------
// Pre-pass: fp32 -> fp16 (Q scaled). One float4 -> one uint2 per thread.
// ---------------------------------------------------------------------------
__global__ void __launch_bounds__(256)
convert_kernel(const float* __restrict__ q, const float* __restrict__ k,
               const float* __restrict__ v, const float* __restrict__ scale_p) {
    const int i = blockIdx.x * 256 + threadIdx.x;   // 0 .. NU2-1
    const float scl = *scale_p;
    float4 fq = reinterpret_cast<const float4*>(q)[i];
    QH[i] = make_uint2(h2(fq.x * scl, fq.y * scl), h2(fq.z * scl, fq.w * scl));
    float4 fk = reinterpret_cast<const float4*>(k)[i];
    KH[i] = make_uint2(h2(fk.x, fk.y), h2(fk.z, fk.w));
    float4 fv = reinterpret_cast<const float4*>(v)[i];
    VH[i] = make_uint2(h2(fv.x, fv.y), h2(fv.z, fv.w));
}

// ---------------------------------------------------------------------------
// One CTA (256 thr, 8 warps) = one (b,h) x one 128-row q-tile. 1 CTA/SM.
// wm = wid&3 (m32 block), wn = wid>>2 (kv group, 32 rows/phase).
// K/V arrive pre-converted fp16 via cp.async (16B chunks) into per-group
// double buffers; no in-loop conversion at all. GEMM1 S(m32 x kv32) via
// ldmatrix; P = relu^2 f16x2 (C->A direct); GEMM2 O(m32 x d128) via
// ldmatrix.trans V (each V frag feeds 2 mma). One 128-wide named bar per
// phase per group. O reduced across the two groups at the end.
// ---------------------------------------------------------------------------
__global__ void __launch_bounds__(NTHREADS, 1)
attn_relu2_kernel(float* __restrict__ out) {
    extern __shared__ uint32_t smw[];
    uint32_t* QW = smw + QS_OFF;

    const int tid  = threadIdx.x;
    const int lane = tid & 31;
    const int g    = lane >> 2;
    const int t4   = lane & 3;
    const int wid  = tid >> 5;
    const int wm   = wid & 3;      // m32 block
    const int wn   = wid >> 2;     // kv group
    const int tid_h = tid & 127;

    const int bh = blockIdx.x >> 4;
    const int q0 = (blockIdx.x & 15) << 7;

    // byte bases of fp16 tensors for this (b,h); one kv row = 256 bytes
    const char* qbh = reinterpret_cast<const char*>(QH) + (size_t)bh * Sdim * 256;
    const char* kbh = reinterpret_cast<const char*>(KH) + (size_t)bh * Sdim * 256;
    const char* vbh = reinterpret_cast<const char*>(VH) + (size_t)bh * Sdim * 256;

    // ldmatrix lane geometry
    const int rl8 = (((lane >> 3) & 1) << 3) + (lane & 7);
    const int c4  = ((lane >> 4) & 1) << 2;

    const uint32_t sb = (uint32_t)__cvta_generic_to_shared(smw);
    const uint32_t qa0 = sb + 4 * (QS_OFF + (wm * 32 + rl8) * WST + c4);
    const uint32_t qa1 = qa0 + 4 * 16 * WST;

    // ---- prologue: cp.async Q tile + K/V tile 0 (buf 0), one group ----
    {
        #pragma unroll
        for (int i = 0; i < 8; i++) {
            int c = tid + NTHREADS * i;       // 0..2047 (128 rows x 16 chunks)
            int r = c >> 4, j = c & 15;
            cp16s(QW + r * WST + 4 * j, qbh + (size_t)(q0 + r) * 256 + 16 * j);
        }
        uint32_t* kd = smw + K16_OFF + (wn * 2 + 0) * 32 * WST;
        uint32_t* vd = smw + V16_OFF + (wn * 2 + 0) * 32 * WST;
        const char* kc = kbh + (size_t)(wn * 32) * 256;
        const char* vc = vbh + (size_t)(wn * 32) * 256;
        #pragma unroll
        for (int i = 0; i < 4; i++) {
            int c = tid_h + 128 * i;          // 0..511 (32 rows x 16 chunks)
            int r = c >> 4, j = c & 15;
            cp16s(kd + r * WST + 4 * j, kc + (size_t)r * 256 + 16 * j);
            cp16s(vd + r * WST + 4 * j, vc + (size_t)r * 256 + 16 * j);
        }
        CP_COMMIT();
        CP_WAIT0();
    }
    __syncthreads();

    float O[2][16][4];
    #pragma unroll
    for (int mb = 0; mb < 2; mb++)
        #pragma unroll
        for (int nd = 0; nd < 16; nd++)
            #pragma unroll
            for (int i = 0; i < 4; i++) O[mb][nd][i] = 0.0f;

    // ---- main loop: 32 phases ----
    #pragma unroll 1
    for (int t = 0; t < NPH; t++) {
        const int buf = t & 1;
        const bool more = (t + 1 < NPH);

        bar_sync(1 + wn, 128);   // fp16[buf] ready; prev reads of buf^1 done

        // issue cp.async for tile t+1 into spare buffer (no register chains)
        if (more) {
            uint32_t* kd = smw + K16_OFF + (wn * 2 + (buf ^ 1)) * 32 * WST;
            uint32_t* vd = smw + V16_OFF + (wn * 2 + (buf ^ 1)) * 32 * WST;
            const char* kc = kbh + (size_t)((t + 1) * PH_KV + wn * 32) * 256;
            const char* vc = vbh + (size_t)((t + 1) * PH_KV + wn * 32) * 256;
            #pragma unroll
            for (int i = 0; i < 4; i++) {
                int c = tid_h + 128 * i;
                int r = c >> 4, j = c & 15;
                cp16s(kd + r * WST + 4 * j, kc + (size_t)r * 256 + 16 * j);
                cp16s(vd + r * WST + 4 * j, vc + (size_t)r * 256 + 16 * j);
            }
            CP_COMMIT();
        }

        const uint32_t kb_b = sb + 4 * (K16_OFF + (wn * 2 + buf) * 32 * WST
                                        + rl8 * WST + c4);
        const uint32_t vb_b = sb + 4 * (V16_OFF + (wn * 2 + buf) * 32 * WST
                                        + rl8 * WST + c4);

        // ---- GEMM1: S(m32 x kv32), 8 k16-steps ----
        float S[2][4][4];
        #pragma unroll
        for (int mb = 0; mb < 2; mb++)
            #pragma unroll
            for (int nb = 0; nb < 4; nb++)
                #pragma unroll
                for (int i = 0; i < 4; i++) S[mb][nb][i] = 0.0f;

        #pragma unroll
        for (int kb = 0; kb < 8; kb++) {
            uint32_t A0[4], A1[4], B0[4], B1[4];
            ldm4(qa0 + 32 * kb, A0);
            ldm4(qa1 + 32 * kb, A1);
            ldm4(kb_b + 32 * kb, B0);
            ldm4(kb_b + 4 * 16 * WST + 32 * kb, B1);
            mma16(S[0][0], A0[0], A0[1], A0[2], A0[3], B0[0], B0[2]);
            mma16(S[0][1], A0[0], A0[1], A0[2], A0[3], B0[1], B0[3]);
            mma16(S[0][2], A0[0], A0[1], A0[2], A0[3], B1[0], B1[2]);
            mma16(S[0][3], A0[0], A0[1], A0[2], A0[3], B1[1], B1[3]);
            mma16(S[1][0], A1[0], A1[1], A1[2], A1[3], B0[0], B0[2]);
            mma16(S[1][1], A1[0], A1[1], A1[2], A1[3], B0[1], B0[3]);
            mma16(S[1][2], A1[0], A1[1], A1[2], A1[3], B1[0], B1[2]);
            mme_guard:
            mma16(S[1][3], A1[0], A1[1], A1[2], A1[3], B1[1], B1[3]);
        }

        // ---- P = relu(S)^2 (f16x2); GEMM2: O += P @ V ----
        #pragma unroll
        for (int s2 = 0; s2 < 2; s2++) {
            uint32_t pA[2][4];
            #pragma unroll
            for (int mb = 0; mb < 2; mb++) {
                pA[mb][0] = hsq(h2(S[mb][2 * s2][0],     S[mb][2 * s2][1]));
                pA[mb][1] = hsq(h2(S[mb][2 * s2][2],     S[mb][2 * s2][3]));
                pA[mb][2] = hsq(h2(S[mb][2 * s2 + 1][0], S[mb][2 * s2 + 1][1]));
                pA[mb][3] = hsq(h2(S[mb][2 * s2 + 1][2], S[mb][2 * s2 + 1][3]));
            }
            const uint32_t va_b = vb_b + 4 * 16 * WST * s2;
            #pragma unroll
            for (int j = 0; j < 8; j++) {
                uint32_t Vr[4];
                ldm4t(va_b + 32 * j, Vr);
                mma16(O[0][2 * j],     pA[0][0], pA[0][1], pA[0][2], pA[0][3], Vr[0], Vr[1]);
                mma16(O[0][2 * j + 1], pA[0][0], pA[0][1], pA[0][2], pA[0][3], Vr[2], Vr[3]);
                mma16(O[1][2 * j],     pA[1][0], pA[1][1], pA[1][2], pA[1][3], Vr[0], Vr[1]);
                mma16(O[1][2 * j + 1], pA[1][0], pA[1][1], pA[1][2], pA[1][3], Vr[2], Vr[3]);
            }
        }

        // transfers for t+1 must land before next phase's bar
        if (more) CP_WAIT0();
    }

    // ---- reduce O across the two kv groups, write out ----
    __syncthreads();
    float* red = reinterpret_cast<float*>(smw);   // 128 x 132 floats
    if (wn == 1) {
        #pragma unroll
        for (int mb = 0; mb < 2; mb++) {
            int r0 = wm * 32 + mb * 16 + g;
            #pragma unroll
            for (int nd = 0; nd < 16; nd++) {
                *reinterpret_cast<float2*>(red + r0 * 132 + nd * 8 + 2 * t4) =
                    make_float2(O[mb][nd][0], O[mb][nd][1]);
                *reinterpret_cast<float2*>(red + (r0 + 8) * 132 + nd * 8 + 2 * t4) =
                    make_float2(O[mb][nd][2], O[mb][nd][3]);
            }
        }
    }
    __syncthreads();
    if (wn == 0) {
        float* ob = out + ((size_t)bh * Sdim + q0) * Ddim;
        #pragma unroll
        for (int mb = 0; mb < 2; mb++) {
            int r0 = wm * 32 + mb * 16 + g;
            #pragma unroll
            for (int nd = 0; nd < 16; nd++) {
                float2 ra = *reinterpret_cast<const float2*>(red + r0 * 132 + nd * 8 + 2 * t4);
                float2 rb = *reinterpret_cast<const float2*>(red + (r0 + 8) * 132 + nd * 8 + 2 * t4);
                *reinterpret_cast<float2*>(ob + r0 * Ddim + nd * 8 + 2 * t4) =
                    make_float2(O[mb][nd][0] + ra.x, O[mb][nd][1] + ra.y);
                *reinterpret_cast<float2*>(ob + (r0 + 8) * Ddim + nd * 8 + 2 * t4) =
                    make_float2(O[mb][nd][2] + rb.x, O[mb][nd][3] + rb.y);
            }
        }
    }
}

extern "C" void kernel_launch(void* const* d_in, const int* in_sizes, int n_in,
                              void* d_out, int out_size) {
    (void)in_sizes; (void)n_in; (void)out_size;
    const float* q = (const float*)d_in[0];
    const float* k = (const float*)d_in[1];
    const float* v = (const float*)d_in[2];
    const float* scale = (const float*)d_in[3];
    float* out = (float*)d_out;

    convert_kernel<<<NU2 / 256, 256>>>(q, k, v, scale);

    cudaFuncSetAttribute(attn_relu2_kernel,
                         cudaFuncAttributeMaxDynamicSharedMemorySize, SMEM_BYTES);
    dim3 grid(Bdim * Hdim * (Sdim / QT));   // 512 CTAs, bh-major
    attn_relu2_kernel<<<grid, NTHREADS, SMEM_BYTES>>>(out);
}

// round 16
// speedup vs baseline: 1.9580x; 1.0038x over previous
#include <cuda_runtime.h>
#include <cstdint>

#define Bdim 2
#define Hdim 16
#define Sdim 2048
#define Ddim 128
#define QT 128            // q-tile rows per CTA
#define PH_KV 64          // kv rows per phase (32 per group)
#define NPH (Sdim / PH_KV)   // 32 phases
#define NTHREADS 256
#define WST 68            // fp16 tile word stride (ldmatrix conflict-free)

#define NTOT (Bdim * Hdim * Sdim * Ddim)      // 8388608 elements per tensor
#define NU2  (NTOT / 4)                       // uint2 (4 halfs) entries

// smem word offsets (all fp16 tiles)
#define QS_OFF  0
#define K16_OFF (QT * WST)                    // 8704
#define V16_OFF (K16_OFF + 4 * 32 * WST)      // K16: 2grp x 2buf x 32 rows
#define SMEM_WORDS (V16_OFF + 4 * 32 * WST)
#define SMEM_BYTES (SMEM_WORDS * 4)           // 104448 B -> 1 CTA/SM

// fp16 copies of Q*scale, K, V (written once by convert_kernel per launch)
__device__ uint2 QH[NU2];
__device__ uint2 KH[NU2];
__device__ uint2 VH[NU2];

// ---------------------------------------------------------------------------
static __device__ __forceinline__ uint32_t h2(float lo, float hi) {
    uint32_t r;
    asm("cvt.rn.f16x2.f32 %0, %1, %2;" : "=r"(r) : "f"(hi), "f"(lo));
    return r;
}
// relu^2 in f16x2
static __device__ __forceinline__ uint32_t hsq(uint32_t w) {
    uint32_t r;
    asm("max.f16x2 %0, %1, %2;" : "=r"(r) : "r"(w), "r"(0u));
    asm("mul.f16x2 %0, %1, %1;" : "=r"(r) : "r"(r));
    return r;
}

static __device__ __forceinline__ void mma16(float* d,
        uint32_t a0, uint32_t a1, uint32_t a2, uint32_t a3,
        uint32_t b0, uint32_t b1) {
    asm volatile(
        "mma.sync.aligned.m16n8k16.row.col.f32.f16.f16.f32 "
        "{%0,%1,%2,%3}, {%4,%5,%6,%7}, {%8,%9}, {%0,%1,%2,%3};"
        : "+f"(d[0]), "+f"(d[1]), "+f"(d[2]), "+f"(d[3])
        : "r"(a0), "r"(a1), "r"(a2), "r"(a3), "r"(b0), "r"(b1));
}

static __device__ __forceinline__ void ldm4(uint32_t addr, uint32_t* r) {
    asm volatile("ldmatrix.sync.aligned.m8n8.x4.shared.b16 {%0,%1,%2,%3}, [%4];"
        : "=r"(r[0]), "=r"(r[1]), "=r"(r[2]), "=r"(r[3]) : "r"(addr));
}
static __device__ __forceinline__ void ldm4t(uint32_t addr, uint32_t* r) {
    asm volatile("ldmatrix.sync.aligned.m8n8.x4.trans.shared.b16 {%0,%1,%2,%3}, [%4];"
        : "=r"(r[0]), "=r"(r[1]), "=r"(r[2]), "=r"(r[3]) : "r"(addr));
}

static __device__ __forceinline__ void cp16s(uint32_t* smem_dst, const void* gsrc) {
    unsigned sa = (unsigned)__cvta_generic_to_shared(smem_dst);
    asm volatile("cp.async.cg.shared.global [%0], [%1], 16;" :: "r"(sa), "l"(gsrc));
}
#define CP_COMMIT() asm volatile("cp.async.commit_group;" ::: "memory")
#define CP_WAIT0()  asm volatile("cp.async.wait_group 0;" ::: "memory")

static __device__ __forceinline__ void bar_sync(int id, int cnt) {
    asm volatile("bar.sync %0, %1;" :: "r"(id), "r"(cnt) : "memory");
}

// ---------------------------------------------------------------------------
// Pre-pass: fp32 -> fp16 (Q scaled). One float4 -> one uint2 per thread.
// ---------------------------------------------------------------------------
__global__ void __launch_bounds__(256)
convert_kernel(const float* __restrict__ q, const float* __restrict__ k,
               const float* __restrict__ v, const float* __restrict__ scale_p) {
    const int i = blockIdx.x * 256 + threadIdx.x;   // 0 .. NU2-1
    const float scl = *scale_p;
    float4 fq = reinterpret_cast<const float4*>(q)[i];
    QH[i] = make_uint2(h2(fq.x * scl, fq.y * scl), h2(fq.z * scl, fq.w * scl));
    float4 fk = reinterpret_cast<const float4*>(k)[i];
    KH[i] = make_uint2(h2(fk.x, fk.y), h2(fk.z, fk.w));
    float4 fv = reinterpret_cast<const float4*>(v)[i];
    VH[i] = make_uint2(h2(fv.x, fv.y), h2(fv.z, fv.w));
}

// ---------------------------------------------------------------------------
// One CTA (256 thr, 8 warps) = one (b,h) x one 128-row q-tile. 1 CTA/SM.
// wm = wid&3 (m32 block), wn = wid>>2 (kv group, 32 rows/phase).
// K/V arrive pre-converted fp16 via cp.async into per-group double buffers.
// Fragments are software-pipelined: ldmatrix for step i+1 issues before the
// mma of step i (GEMM1: A/B double-buffered; GEMM2: V double-buffered, all
// pA converted upfront). One 128-wide named bar per phase per group.
// O reduced across the two groups at the end.
// ---------------------------------------------------------------------------
__global__ void __launch_bounds__(NTHREADS, 1)
attn_relu2_kernel(float* __restrict__ out) {
    extern __shared__ uint32_t smw[];
    uint32_t* QW = smw + QS_OFF;

    const int tid  = threadIdx.x;
    const int lane = tid & 31;
    const int g    = lane >> 2;
    const int t4   = lane & 3;
    const int wid  = tid >> 5;
    const int wm   = wid & 3;      // m32 block
    const int wn   = wid >> 2;     // kv group
    const int tid_h = tid & 127;

    const int bh = blockIdx.x >> 4;
    const int q0 = (blockIdx.x & 15) << 7;

    // byte bases of fp16 tensors for this (b,h); one kv row = 256 bytes
    const char* qbh = reinterpret_cast<const char*>(QH) + (size_t)bh * Sdim * 256;
    const char* kbh = reinterpret_cast<const char*>(KH) + (size_t)bh * Sdim * 256;
    const char* vbh = reinterpret_cast<const char*>(VH) + (size_t)bh * Sdim * 256;

    // ldmatrix lane geometry
    const int rl8 = (((lane >> 3) & 1) << 3) + (lane & 7);
    const int c4  = ((lane >> 4) & 1) << 2;

    const uint32_t sb = (uint32_t)__cvta_generic_to_shared(smw);
    const uint32_t qa0 = sb + 4 * (QS_OFF + (wm * 32 + rl8) * WST + c4);
    const uint32_t qa1 = qa0 + 4 * 16 * WST;

    // ---- prologue: cp.async Q tile + K/V tile 0 (buf 0) ----
    {
        #pragma unroll
        for (int i = 0; i < 8; i++) {
            int c = tid + NTHREADS * i;       // 0..2047 (128 rows x 16 chunks)
            int r = c >> 4, j = c & 15;
            cp16s(QW + r * WST + 4 * j, qbh + (size_t)(q0 + r) * 256 + 16 * j);
        }
        uint32_t* kd = smw + K16_OFF + (wn * 2 + 0) * 32 * WST;
        uint32_t* vd = smw + V16_OFF + (wn * 2 + 0) * 32 * WST;
        const char* kc = kbh + (size_t)(wn * 32) * 256;
        const char* vc = vbh + (size_t)(wn * 32) * 256;
        #pragma unroll
        for (int i = 0; i < 4; i++) {
            int c = tid_h + 128 * i;          // 0..511 (32 rows x 16 chunks)
            int r = c >> 4, j = c & 15;
            cp16s(kd + r * WST + 4 * j, kc + (size_t)r * 256 + 16 * j);
            cp16s(vd + r * WST + 4 * j, vc + (size_t)r * 256 + 16 * j);
        }
        CP_COMMIT();
        CP_WAIT0();
    }
    __syncthreads();

    float O[2][16][4];
    #pragma unroll
    for (int mb = 0; mb < 2; mb++)
        #pragma unroll
        for (int nd = 0; nd < 16; nd++)
            #pragma unroll
            for (int i = 0; i < 4; i++) O[mb][nd][i] = 0.0f;

    // ---- main loop: 32 phases ----
    #pragma unroll 1
    for (int t = 0; t < NPH; t++) {
        const int buf = t & 1;
        const bool more = (t + 1 < NPH);

        bar_sync(1 + wn, 128);   // fp16[buf] ready; prev reads of buf^1 done

        // issue cp.async for tile t+1 into spare buffer (no register chains)
        if (more) {
            uint32_t* kd = smw + K16_OFF + (wn * 2 + (buf ^ 1)) * 32 * WST;
            uint32_t* vd = smw + V16_OFF + (wn * 2 + (buf ^ 1)) * 32 * WST;
            const char* kc = kbh + (size_t)((t + 1) * PH_KV + wn * 32) * 256;
            const char* vc = vbh + (size_t)((t + 1) * PH_KV + wn * 32) * 256;
            #pragma unroll
            for (int i = 0; i < 4; i++) {
                int c = tid_h + 128 * i;
                int r = c >> 4, j = c & 15;
                cp16s(kd + r * WST + 4 * j, kc + (size_t)r * 256 + 16 * j);
                cp16s(vd + r * WST + 4 * j, vc + (size_t)r * 256 + 16 * j);
            }
            CP_COMMIT();
        }

        const uint32_t kb_b = sb + 4 * (K16_OFF + (wn * 2 + buf) * 32 * WST
                                        + rl8 * WST + c4);
        const uint32_t vb_b = sb + 4 * (V16_OFF + (wn * 2 + buf) * 32 * WST
                                        + rl8 * WST + c4);

        // ---- GEMM1: S(m32 x kv32), 8 k16-steps, fragments pipelined ----
        float S[2][4][4];
        #pragma unroll
        for (int mb = 0; mb < 2; mb++)
            #pragma unroll
            for (int nb = 0; nb < 4; nb++)
                #pragma unroll
                for (int i = 0; i < 4; i++) S[mb][nb][i] = 0.0f;

        uint32_t A0[2][4], A1[2][4], B0[2][4], B1[2][4];
        ldm4(qa0, A0[0]);
        ldm4(qa1, A1[0]);
        ldm4(kb_b, B0[0]);
        ldm4(kb_b + 4 * 16 * WST, B1[0]);

        #pragma unroll
        for (int kb = 0; kb < 8; kb++) {
            const int cur = kb & 1, nxt = cur ^ 1;
            if (kb < 7) {
                ldm4(qa0 + 32 * (kb + 1), A0[nxt]);
                ldm4(qa1 + 32 * (kb + 1), A1[nxt]);
                ldm4(kb_b + 32 * (kb + 1), B0[nxt]);
                ldm4(kb_b + 4 * 16 * WST + 32 * (kb + 1), B1[nxt]);
            }
            mma16(S[0][0], A0[cur][0], A0[cur][1], A0[cur][2], A0[cur][3], B0[cur][0], B0[cur][2]);
            mma16(S[0][1], A0[cur][0], A0[cur][1], A0[cur][2], A0[cur][3], B0[cur][1], B0[cur][3]);
            mma16(S[0][2], A0[cur][0], A0[cur][1], A0[cur][2], A0[cur][3], B1[cur][0], B1[cur][2]);
            mma16(S[0][3], A0[cur][0], A0[cur][1], A0[cur][2], A0[cur][3], B1[cur][1], B1[cur][3]);
            mma16(S[1][0], A1[cur][0], A1[cur][1], A1[cur][2], A1[cur][3], B0[cur][0], B0[cur][2]);
            mma16(S[1][1], A1[cur][0], A1[cur][1], A1[cur][2], A1[cur][3], B0[cur][1], B0[cur][3]);
            mma16(S[1][2], A1[cur][0], A1[cur][1], A1[cur][2], A1[cur][3], B1[cur][0], B1[cur][2]);
            mma16(S[1][3], A1[cur][0], A1[cur][1], A1[cur][2], A1[cur][3], B1[cur][1], B1[cur][3]);
        }

        // ---- GEMM2: O += relu(S)^2 @ V, flattened + V pipelined ----
        uint32_t Vr[2][4];
        ldm4t(vb_b, Vr[0]);          // first V frag; independent of S

        uint32_t pA[2][2][4];        // [s2][mb]
        #pragma unroll
        for (int s2 = 0; s2 < 2; s2++)
            #pragma unroll
            for (int mb = 0; mb < 2; mb++) {
                pA[s2][mb][0] = hsq(h2(S[mb][2 * s2][0],     S[mb][2 * s2][1]));
                pA[s2][mb][1] = hsq(h2(S[mb][2 * s2][2],     S[mb][2 * s2][3]));
                pA[s2][mb][2] = hsq(h2(S[mb][2 * s2 + 1][0], S[mb][2 * s2 + 1][1]));
                pA[s2][mb][3] = hsq(h2(S[mb][2 * s2 + 1][2], S[mb][2 * s2 + 1][3]));
            }

        #pragma unroll
        for (int jj = 0; jj < 16; jj++) {
            const int cur = jj & 1, nxt = cur ^ 1;
            if (jj < 15) {
                const int j1 = jj + 1;
                ldm4t(vb_b + 4 * 16 * WST * (j1 >> 3) + 32 * (j1 & 7), Vr[nxt]);
            }
            const int s2 = jj >> 3, j = jj & 7;
            mma16(O[0][2 * j],     pA[s2][0][0], pA[s2][0][1], pA[s2][0][2], pA[s2][0][3], Vr[cur][0], Vr[cur][1]);
            mma16(O[0][2 * j + 1], pA[s2][0][0], pA[s2][0][1], pA[s2][0][2], pA[s2][0][3], Vr[cur][2], Vr[cur][3]);
            mma16(O[1][2 * j],     pA[s2][1][0], pA[s2][1][1], pA[s2][1][2], pA[s2][1][3], Vr[cur][0], Vr[cur][1]);
            mma16(O[1][2 * j + 1], pA[s2][1][0], pA[s2][1][1], pA[s2][1][2], pA[s2][1][3], Vr[cur][2], Vr[cur][3]);
        }

        // transfers for t+1 must land before next phase's bar
        if (more) CP_WAIT0();
    }

    // ---- reduce O across the two kv groups, write out ----
    __syncthreads();
    float* red = reinterpret_cast<float*>(smw);   // 128 x 132 floats
    if (wn == 1) {
        #pragma unroll
        for (int mb = 0; mb < 2; mb++) {
            int r0 = wm * 32 + mb * 16 + g;
            #pragma unroll
            for (int nd = 0; nd < 16; nd++) {
                *reinterpret_cast<float2*>(red + r0 * 132 + nd * 8 + 2 * t4) =
                    make_float2(O[mb][nd][0], O[mb][nd][1]);
                *reinterpret_cast<float2*>(red + (r0 + 8) * 132 + nd * 8 + 2 * t4) =
                    make_float2(O[mb][nd][2], O[mb][nd][3]);
            }
        }
    }
    __syncthreads();
    if (wn == 0) {
        float* ob = out + ((size_t)bh * Sdim + q0) * Ddim;
        #pragma unroll
        for (int mb = 0; mb < 2; mb++) {
            int r0 = wm * 32 + mb * 16 + g;
            #pragma unroll
            for (int nd = 0; nd < 16; nd++) {
                float2 ra = *reinterpret_cast<const float2*>(red + r0 * 132 + nd * 8 + 2 * t4);
                float2 rb = *reinterpret_cast<const float2*>(red + (r0 + 8) * 132 + nd * 8 + 2 * t4);
                *reinterpret_cast<float2*>(ob + r0 * Ddim + nd * 8 + 2 * t4) =
                    make_float2(O[mb][nd][0] + ra.x, O[mb][nd][1] + ra.y);
                *reinterpret_cast<float2*>(ob + (r0 + 8) * Ddim + nd * 8 + 2 * t4) =
                    make_float2(O[mb][nd][2] + rb.x, O[mb][nd][3] + rb.y);
            }
        }
    }
}

extern "C" void kernel_launch(void* const* d_in, const int* in_sizes, int n_in,
                              void* d_out, int out_size) {
    (void)in_sizes; (void)n_in; (void)out_size;
    const float* q = (const float*)d_in[0];
    const float* k = (const float*)d_in[1];
    const float* v = (const float*)d_in[2];
    const float* scale = (const float*)d_in[3];
    float* out = (float*)d_out;

    convert_kernel<<<NU2 / 256, 256>>>(q, k, v, scale);

    cudaFuncSetAttribute(attn_relu2_kernel,
                         cudaFuncAttributeMaxDynamicSharedMemorySize, SMEM_BYTES);
    dim3 grid(Bdim * Hdim * (Sdim / QT));   // 512 CTAs, bh-major
    attn_relu2_kernel<<<grid, NTHREADS, SMEM_BYTES>>>(out);
}

// round 17
// speedup vs baseline: 2.0042x; 1.0236x over previous
#include <cuda_runtime.h>
#include <cstdint>

#define Bdim 2
#define Hdim 16
#define Sdim 2048
#define Ddim 128
#define QT 64             // q-tile rows per CTA
#define NPH 32            // phases; each group consumes 16 kv rows per phase
#define NTHREADS 256
#define WST 68            // fp16 tile word stride (ldmatrix conflict-free)

#define NTOT (Bdim * Hdim * Sdim * Ddim)      // 8388608 elements per tensor
#define NU2  (NTOT / 4)                       // uint2 (4 halfs) entries

// smem word offsets (all fp16 tiles)
#define QS_OFF  0
#define K16_OFF (QT * WST)                    // 4352
#define V16_OFF (K16_OFF + 8 * 16 * WST)      // K16: 4grp x 2buf x 16 rows
#define SMEM_WORDS (V16_OFF + 8 * 16 * WST)   // V16: same
#define SMEM_BYTES (SMEM_WORDS * 4)           // 87040 B

// fp16 copies of Q*scale, K, V (written once by convert_kernel per launch)
__device__ uint2 QH[NU2];
__device__ uint2 KH[NU2];
__device__ uint2 VH[NU2];

// ---------------------------------------------------------------------------
static __device__ __forceinline__ uint32_t h2(float lo, float hi) {
    uint32_t r;
    asm("cvt.rn.f16x2.f32 %0, %1, %2;" : "=r"(r) : "f"(hi), "f"(lo));
    return r;
}
// relu^2 in f16x2
static __device__ __forceinline__ uint32_t hsq(uint32_t w) {
    uint32_t r;
    asm("max.f16x2 %0, %1, %2;" : "=r"(r) : "r"(w), "r"(0u));
    asm("mul.f16x2 %0, %1, %1;" : "=r"(r) : "r"(r));
    return r;
}

static __device__ __forceinline__ void mma16(float* d,
        uint32_t a0, uint32_t a1, uint32_t a2, uint32_t a3,
        uint32_t b0, uint32_t b1) {
    asm volatile(
        "mma.sync.aligned.m16n8k16.row.col.f32.f16.f16.f32 "
        "{%0,%1,%2,%3}, {%4,%5,%6,%7}, {%8,%9}, {%0,%1,%2,%3};"
        : "+f"(d[0]), "+f"(d[1]), "+f"(d[2]), "+f"(d[3])
        : "r"(a0), "r"(a1), "r"(a2), "r"(a3), "r"(b0), "r"(b1));
}

static __device__ __forceinline__ void ldm4(uint32_t addr, uint32_t* r) {
    asm volatile("ldmatrix.sync.aligned.m8n8.x4.shared.b16 {%0,%1,%2,%3}, [%4];"
        : "=r"(r[0]), "=r"(r[1]), "=r"(r[2]), "=r"(r[3]) : "r"(addr));
}
static __device__ __forceinline__ void ldm4t(uint32_t addr, uint32_t* r) {
    asm volatile("ldmatrix.sync.aligned.m8n8.x4.trans.shared.b16 {%0,%1,%2,%3}, [%4];"
        : "=r"(r[0]), "=r"(r[1]), "=r"(r[2]), "=r"(r[3]) : "r"(addr));
}

static __device__ __forceinline__ void cp16s(uint32_t* smem_dst, const void* gsrc) {
    unsigned sa = (unsigned)__cvta_generic_to_shared(smem_dst);
    asm volatile("cp.async.cg.shared.global [%0], [%1], 16;" :: "r"(sa), "l"(gsrc));
}
#define CP_COMMIT() asm volatile("cp.async.commit_group;" ::: "memory")
#define CP_WAIT0()  asm volatile("cp.async.wait_group 0;" ::: "memory")

static __device__ __forceinline__ void bar_sync(int id, int cnt) {
    asm volatile("bar.sync %0, %1;" :: "r"(id), "r"(cnt) : "memory");
}

// ---------------------------------------------------------------------------
// Pre-pass: fp32 -> fp16 (Q scaled). One float4 -> one uint2 per thread.
// ---------------------------------------------------------------------------
__global__ void __launch_bounds__(256)
convert_kernel(const float* __restrict__ q, const float* __restrict__ k,
               const float* __restrict__ v, const float* __restrict__ scale_p) {
    const int i = blockIdx.x * 256 + threadIdx.x;   // 0 .. NU2-1
    const float scl = *scale_p;
    float4 fq = reinterpret_cast<const float4*>(q)[i];
    QH[i] = make_uint2(h2(fq.x * scl, fq.y * scl), h2(fq.z * scl, fq.w * scl));
    float4 fk = reinterpret_cast<const float4*>(k)[i];
    KH[i] = make_uint2(h2(fk.x, fk.y), h2(fk.z, fk.w));
    float4 fv = reinterpret_cast<const float4*>(v)[i];
    VH[i] = make_uint2(h2(fv.x, fv.y), h2(fv.z, fv.w));
}

// ---------------------------------------------------------------------------
// One CTA (256 thr, 8 warps) = one (b,h) x one 64-row q-tile. 1024 CTAs ->
// 6.92 waves (quantization loss ~1%). wm = wid&1 (m32 block), wn = wid>>1
// (kv group 0..3, 16 rows/phase, 64-wide named bar, own double buffers).
// GEMM1 S(m32 x kv16) via ldmatrix (pipelined); P = relu^2 f16x2 (C->A
// direct, one k16 step); GEMM2 O(m32 x d128) via ldmatrix.trans V.
// O reduced across the 4 groups via a two-round smem tree at the end.
// ---------------------------------------------------------------------------
__global__ void __launch_bounds__(NTHREADS, 1)
attn_relu2_kernel(float* __restrict__ out) {
    extern __shared__ uint32_t smw[];
    uint32_t* QW = smw + QS_OFF;

    const int tid  = threadIdx.x;
    const int lane = tid & 31;
    const int g    = lane >> 2;
    const int t4   = lane & 3;
    const int wid  = tid >> 5;
    const int wm   = wid & 1;      // m32 block (rows wm*32..+31)
    const int wn   = wid >> 1;     // kv group 0..3
    const int tid_q = tid & 63;    // thread id within group

    const int bh = blockIdx.x >> 5;
    const int q0 = (blockIdx.x & 31) << 6;

    // byte bases of fp16 tensors for this (b,h); one row = 256 bytes
    const char* qbh = reinterpret_cast<const char*>(QH) + (size_t)bh * Sdim * 256;
    const char* kbh = reinterpret_cast<const char*>(KH) + (size_t)bh * Sdim * 256;
    const char* vbh = reinterpret_cast<const char*>(VH) + (size_t)bh * Sdim * 256;

    // ldmatrix lane geometry
    const int rl8 = (((lane >> 3) & 1) << 3) + (lane & 7);
    const int c4  = ((lane >> 4) & 1) << 2;

    const uint32_t sb = (uint32_t)__cvta_generic_to_shared(smw);
    const uint32_t qa0 = sb + 4 * (QS_OFF + (wm * 32 + rl8) * WST + c4);
    const uint32_t qa1 = qa0 + 4 * 16 * WST;

    // ---- prologue: cp.async Q tile + K/V tile 0 (buf 0) ----
    {
        #pragma unroll
        for (int i = 0; i < 4; i++) {
            int c = tid + NTHREADS * i;       // 0..1023 (64 rows x 16 chunks)
            int r = c >> 4, j = c & 15;
            cp16s(QW + r * WST + 4 * j, qbh + (size_t)(q0 + r) * 256 + 16 * j);
        }
        uint32_t* kd = smw + K16_OFF + (wn * 2 + 0) * 16 * WST;
        uint32_t* vd = smw + V16_OFF + (wn * 2 + 0) * 16 * WST;
        const char* kc = kbh + (size_t)(wn * 16) * 256;
        const char* vc = vbh + (size_t)(wn * 16) * 256;
        #pragma unroll
        for (int i = 0; i < 4; i++) {
            int c = tid_q + 64 * i;           // 0..255 (16 rows x 16 chunks)
            int r = c >> 4, j = c & 15;
            cp16s(kd + r * WST + 4 * j, kc + (size_t)r * 256 + 16 * j);
            cp16s(vd + r * WST + 4 * j, vc + (size_t)r * 256 + 16 * j);
        }
        CP_COMMIT();
        CP_WAIT0();
    }
    __syncthreads();

    float O[2][16][4];
    #pragma unroll
    for (int mb = 0; mb < 2; mb++)
        #pragma unroll
        for (int nd = 0; nd < 16; nd++)
            #pragma unroll
            for (int i = 0; i < 4; i++) O[mb][nd][i] = 0.0f;

    // ---- main loop: 32 phases of kv16 per group ----
    #pragma unroll 1
    for (int t = 0; t < NPH; t++) {
        const int buf = t & 1;
        const bool more = (t + 1 < NPH);

        bar_sync(1 + wn, 64);   // fp16[buf] ready; prev reads of buf^1 done

        // issue cp.async for tile t+1 into spare buffer
        if (more) {
            uint32_t* kd = smw + K16_OFF + (wn * 2 + (buf ^ 1)) * 16 * WST;
            uint32_t* vd = smw + V16_OFF + (wn * 2 + (buf ^ 1)) * 16 * WST;
            const char* kc = kbh + (size_t)((t + 1) * 64 + wn * 16) * 256;
            const char* vc = vbh + (size_t)((t + 1) * 64 + wn * 16) * 256;
            #pragma unroll
            for (int i = 0; i < 4; i++) {
                int c = tid_q + 64 * i;
                int r = c >> 4, j = c & 15;
                cp16s(kd + r * WST + 4 * j, kc + (size_t)r * 256 + 16 * j);
                cp16s(vd + r * WST + 4 * j, vc + (size_t)r * 256 + 16 * j);
            }
            CP_COMMIT();
        }

        const uint32_t kb_b = sb + 4 * (K16_OFF + (wn * 2 + buf) * 16 * WST
                                        + rl8 * WST + c4);
        const uint32_t vb_b = sb + 4 * (V16_OFF + (wn * 2 + buf) * 16 * WST
                                        + rl8 * WST + c4);

        // ---- GEMM1: S(m32 x kv16), 8 k16-steps, fragments pipelined ----
        float S[2][2][4];
        #pragma unroll
        for (int mb = 0; mb < 2; mb++)
            #pragma unroll
            for (int nb = 0; nb < 2; nb++)
                #pragma unroll
                for (int i = 0; i < 4; i++) S[mb][nb][i] = 0.0f;

        uint32_t A0[2][4], A1[2][4], Bf[2][4];
        ldm4(qa0, A0[0]);
        ldm4(qa1, A1[0]);
        ldm4(kb_b, Bf[0]);

        #pragma unroll
        for (int kb = 0; kb < 8; kb++) {
            const int cur = kb & 1, nxt = cur ^ 1;
            if (kb < 7) {
                ldm4(qa0 + 32 * (kb + 1), A0[nxt]);
                ldm4(qa1 + 32 * (kb + 1), A1[nxt]);
                ldm4(kb_b + 32 * (kb + 1), Bf[nxt]);
            }
            mma16(S[0][0], A0[cur][0], A0[cur][1], A0[cur][2], A0[cur][3], Bf[cur][0], Bf[cur][2]);
            mma16(S[0][1], A0[cur][0], A0[cur][1], A0[cur][2], A0[cur][3], Bf[cur][1], Bf[cur][3]);
            mma16(S[1][0], A1[cur][0], A1[cur][1], A1[cur][2], A1[cur][3], Bf[cur][0], Bf[cur][2]);
            mma16(S[1][1], A1[cur][0], A1[cur][1], A1[cur][2], A1[cur][3], Bf[cur][1], Bf[cur][3]);
        }

        // ---- P = relu(S)^2 (one k16 step); GEMM2: O += P @ V, V pipelined ----
        uint32_t Vr[2][4];
        ldm4t(vb_b, Vr[0]);          // first V frag; independent of S

        uint32_t pA[2][4];
        #pragma unroll
        for (int mb = 0; mb < 2; mb++) {
            pA[mb][0] = hsq(h2(S[mb][0][0], S[mb][0][1]));
            pA[mb][1] = hsq(h2(S[mb][0][2], S[mb][0][3]));
            pA[mb][2] = hsq(h2(S[mb][1][0], S[mb][1][1]));
            pA[mb][3] = hsq(h2(S[mb][1][2], S[mb][1][3]));
        }

        #pragma unroll
        for (int jj = 0; jj < 8; jj++) {
            const int cur = jj & 1, nxt = cur ^ 1;
            if (jj < 7) ldm4t(vb_b + 32 * (jj + 1), Vr[nxt]);
            mma16(O[0][2 * jj],     pA[0][0], pA[0][1], pA[0][2], pA[0][3], Vr[cur][0], Vr[cur][1]);
            mma16(O[0][2 * jj + 1], pA[0][0], pA[0][1], pA[0][2], pA[0][3], Vr[cur][2], Vr[cur][3]);
            mma16(O[1][2 * jj],     pA[1][0], pA[1][1], pA[1][2], pA[1][3], Vr[cur][0], Vr[cur][1]);
            mma16(O[1][2 * jj + 1], pA[1][0], pA[1][1], pA[1][2], pA[1][3], Vr[cur][2], Vr[cur][3]);
        }

        if (more) CP_WAIT0();
    }

    // ---- reduce O across the 4 kv groups (two-round smem tree) ----
    float* red0 = reinterpret_cast<float*>(smw);          // 64 x 132 floats
    float* red1 = reinterpret_cast<float*>(smw) + 8448;   // second buffer

#define WRITE_PART(dst) do { \
    _Pragma("unroll") \
    for (int mb = 0; mb < 2; mb++) { \
        int r0 = wm * 32 + mb * 16 + g; \
        _Pragma("unroll") \
        for (int nd = 0; nd < 16; nd++) { \
            *reinterpret_cast<float2*>((dst) + r0 * 132 + nd * 8 + 2 * t4) = \
                make_float2(O[mb][nd][0], O[mb][nd][1]); \
            *reinterpret_cast<float2*>((dst) + (r0 + 8) * 132 + nd * 8 + 2 * t4) = \
                make_float2(O[mb][nd][2], O[mb][nd][3]); \
        } } } while (0)

#define ADD_PART(src) do { \
    _Pragma("unroll") \
    for (int mb = 0; mb < 2; mb++) { \
        int r0 = wm * 32 + mb * 16 + g; \
        _Pragma("unroll") \
        for (int nd = 0; nd < 16; nd++) { \
            float2 ra = *reinterpret_cast<const float2*>((src) + r0 * 132 + nd * 8 + 2 * t4); \
            float2 rb = *reinterpret_cast<const float2*>((src) + (r0 + 8) * 132 + nd * 8 + 2 * t4); \
            O[mb][nd][0] += ra.x; O[mb][nd][1] += ra.y; \
            O[mb][nd][2] += rb.x; O[mb][nd][3] += rb.y; \
        } } } while (0)

    __syncthreads();
    if (wn == 1) WRITE_PART(red0);
    if (wn == 3) WRITE_PART(red1);
    __syncthreads();
    if (wn == 0) ADD_PART(red0);
    if (wn == 2) ADD_PART(red1);
    __syncthreads();
    if (wn == 2) WRITE_PART(red0);
    __syncthreads();
    if (wn == 0) {
        ADD_PART(red0);
        float* ob = out + ((size_t)bh * Sdim + q0) * Ddim;
        #pragma unroll
        for (int mb = 0; mb < 2; mb++) {
            int r0 = wm * 32 + mb * 16 + g;
            #pragma unroll
            for (int nd = 0; nd < 16; nd++) {
                *reinterpret_cast<float2*>(ob + r0 * Ddim + nd * 8 + 2 * t4) =
                    make_float2(O[mb][nd][0], O[mb][nd][1]);
                *reinterpret_cast<float2*>(ob + (r0 + 8) * Ddim + nd * 8 + 2 * t4) =
                    make_float2(O[mb][nd][2], O[mb][nd][3]);
            }
        }
    }
}

extern "C" void kernel_launch(void* const* d_in, const int* in_sizes, int n_in,
                              void* d_out, int out_size) {
    (void)in_sizes; (void)n_in; (void)out_size;
    const float* q = (const float*)d_in[0];
    const float* k = (const float*)d_in[1];
    const float* v = (const float*)d_in[2];
    const float* scale = (const float*)d_in[3];
    float* out = (float*)d_out;

    convert_kernel<<<NU2 / 256, 256>>>(q, k, v, scale);

    cudaFuncSetAttribute(attn_relu2_kernel,
                         cudaFuncAttributeMaxDynamicSharedMemorySize, SMEM_BYTES);
    dim3 grid(Bdim * Hdim * (Sdim / QT));   // 1024 CTAs, bh-major
    attn_relu2_kernel<<<grid, NTHREADS, SMEM_BYTES>>>(out);
}